// round 2
// baseline (speedup 1.0000x reference)
#include <cuda_runtime.h>
#include <math.h>

#define NPTS 1024
#define KNB 20
#define BATCH 8
#define CEPS 1e-5f
#define CSLOPE 0.2f

// ---------------- scratch (no allocations allowed) ----------------
__device__ float g_cat[(size_t)BATCH * 512 * NPTS];   // x1(0:64) x2(64:128) x3(128:256) x4(256:512)
__device__ int   g_idx[(size_t)BATCH * NPTS * KNB];
__device__ float g_h0[BATCH * 2048];
__device__ float g_h1[BATCH * 512];
__device__ float g_h2[BATCH * 256];

// ---------------- kNN: one block per (b, n) ----------------
// dist[m] = 2*dot(x_n,x_m) - ||x_n||^2 - ||x_m||^2  (matches ref pd up to dot order)
// top-20 via 20 iterations of masked argmax (larger value wins; tie -> lower index,
// matching jax.lax.top_k). Self-distance is exactly 0 because dot and xx use the
// identical fma sequence.
template<int C>
__global__ void knn_kernel(const float* __restrict__ xin, int cin_off) {
    const int b = blockIdx.y, n = blockIdx.x, tid = threadIdx.x;
    const float* xb = xin ? (xin + (size_t)b * C * NPTS)
                          : (g_cat + (size_t)b * 512 * NPTS + (size_t)cin_off * NPTS);
    __shared__ float ctr[C];
    __shared__ float dist[NPTS];
    __shared__ float rv[256];
    __shared__ int   ri[256];

    for (int c = tid; c < C; c += 256) ctr[c] = xb[c * NPTS + n];
    __syncthreads();

    float xxn = 0.f;
    #pragma unroll
    for (int c = 0; c < C; c++) xxn = fmaf(ctr[c], ctr[c], xxn);

    for (int m = tid; m < NPTS; m += 256) {
        float dot = 0.f, xxm = 0.f;
        #pragma unroll 4
        for (int c = 0; c < C; c++) {
            float v = xb[c * NPTS + m];
            dot = fmaf(v, ctr[c], dot);
            xxm = fmaf(v, v, xxm);
        }
        dist[m] = 2.f * dot - xxn - xxm;
    }
    __syncthreads();

    int* myidx = g_idx + ((size_t)b * NPTS + n) * KNB;
    for (int k = 0; k < KNB; k++) {
        float bv = -INFINITY; int bi = NPTS;
        for (int m = tid; m < NPTS; m += 256) {
            float v = dist[m];
            if (v > bv) { bv = v; bi = m; }   // strict > keeps lowest index on ties
        }
        rv[tid] = bv; ri[tid] = bi;
        __syncthreads();
        for (int s = 128; s > 0; s >>= 1) {
            if (tid < s) {
                float ov = rv[tid + s]; int oi = ri[tid + s];
                if (ov > rv[tid] || (ov == rv[tid] && oi < ri[tid])) { rv[tid] = ov; ri[tid] = oi; }
            }
            __syncthreads();
        }
        if (tid == 0) { myidx[k] = ri[0]; dist[ri[0]] = -INFINITY; }
        __syncthreads();
    }
}

// ---------------- edge conv block: one block per (b, n), one thread per out channel ----------------
// y[o,k] = sum_c w[o,c]*nbr[k][c] + sum_c (w[o,C+c]-w[o,c])*ctr[c]
// then BN + leaky ReLU + max over k.
template<int C, int O>
__global__ void conv_kernel(const float* __restrict__ xin,
                            const float* __restrict__ w,
                            const float* __restrict__ bnp,
                            int cin_off, int cout_off) {
    const int b = blockIdx.y, n = blockIdx.x, tid = threadIdx.x;
    const float* xb = xin ? (xin + (size_t)b * C * NPTS)
                          : (g_cat + (size_t)b * 512 * NPTS + (size_t)cin_off * NPTS);
    __shared__ float ctr[C];
    __shared__ float nbr[KNB][C];
    __shared__ int   jid[KNB];

    for (int c = tid; c < C; c += O) ctr[c] = xb[c * NPTS + n];
    if (tid < KNB) jid[tid] = g_idx[((size_t)b * NPTS + n) * KNB + tid];
    __syncthreads();
    for (int t = tid; t < KNB * C; t += O) {
        int k = t / C, c = t - k * C;
        nbr[k][c] = xb[c * NPTS + jid[k]];
    }
    __syncthreads();

    const int o = tid;
    const float* wr = w + (size_t)o * 2 * C;

    float base = 0.f;
    #pragma unroll 4
    for (int c = 0; c < C; c++) base = fmaf(wr[C + c] - wr[c], ctr[c], base);

    float acc[KNB];
    #pragma unroll
    for (int k = 0; k < KNB; k++) acc[k] = base;

    if (C % 4 == 0) {
        for (int c = 0; c < C; c += 4) {
            float4 wv = *reinterpret_cast<const float4*>(wr + c);
            #pragma unroll
            for (int k = 0; k < KNB; k++) {
                float4 nv = *reinterpret_cast<const float4*>(&nbr[k][c & (C - 1)]);
                acc[k] = fmaf(wv.x, nv.x, acc[k]);
                acc[k] = fmaf(wv.y, nv.y, acc[k]);
                acc[k] = fmaf(wv.z, nv.z, acc[k]);
                acc[k] = fmaf(wv.w, nv.w, acc[k]);
            }
        }
    } else {
        for (int c = 0; c < C; c++) {
            float wv = wr[c];
            #pragma unroll
            for (int k = 0; k < KNB; k++) acc[k] = fmaf(wv, nbr[k][c], acc[k]);
        }
    }

    float gg = bnp[o], bb = bnp[O + o], mm = bnp[2 * O + o], vv = bnp[3 * O + o];
    float scale = gg / sqrtf(vv + CEPS);
    float best = -INFINITY;
    #pragma unroll
    for (int k = 0; k < KNB; k++) {
        float y = (acc[k] - mm) * scale + bb;
        y = (y > 0.f) ? y : CSLOPE * y;
        best = fmaxf(best, y);
    }
    g_cat[(size_t)b * 512 * NPTS + (size_t)(cout_off + o) * NPTS + n] = best;
}

// ---------------- embedding (cat[512] -> 1024) + BN + lrelu + max/mean pools ----------------
// One block per (b, group of 8 output channels). Thread t handles points 4t..4t+3 (float4).
__global__ void edge_kernel(const float* __restrict__ we, const float* __restrict__ bne) {
    const int b = blockIdx.y, tid = threadIdx.x;
    const int o0 = blockIdx.x * 8;
    __shared__ float ws[8][512];
    for (int t = tid; t < 8 * 512; t += 256)
        ws[t >> 9][t & 511] = we[(size_t)(o0 + (t >> 9)) * 512 + (t & 511)];
    __syncthreads();

    const float* catb = g_cat + (size_t)b * 512 * NPTS;
    const int n0 = tid * 4;

    float acc[8][4];
    #pragma unroll
    for (int j = 0; j < 8; j++)
        acc[j][0] = acc[j][1] = acc[j][2] = acc[j][3] = 0.f;

    for (int c = 0; c < 512; c++) {
        float4 xv = *reinterpret_cast<const float4*>(catb + (size_t)c * NPTS + n0);
        #pragma unroll
        for (int j = 0; j < 8; j++) {
            float wv = ws[j][c];
            acc[j][0] = fmaf(wv, xv.x, acc[j][0]);
            acc[j][1] = fmaf(wv, xv.y, acc[j][1]);
            acc[j][2] = fmaf(wv, xv.z, acc[j][2]);
            acc[j][3] = fmaf(wv, xv.w, acc[j][3]);
        }
    }

    __shared__ float red[256];
    #pragma unroll
    for (int j = 0; j < 8; j++) {
        const int o = o0 + j;
        float gg = bne[o], bb = bne[1024 + o], mm = bne[2048 + o], vv = bne[3072 + o];
        float scale = gg / sqrtf(vv + CEPS);
        float mx = -INFINITY, sm = 0.f;
        #pragma unroll
        for (int q = 0; q < 4; q++) {
            float y = (acc[j][q] - mm) * scale + bb;
            y = (y > 0.f) ? y : CSLOPE * y;
            mx = fmaxf(mx, y);
            sm += y;
        }
        red[tid] = mx; __syncthreads();
        for (int s = 128; s > 0; s >>= 1) { if (tid < s) red[tid] = fmaxf(red[tid], red[tid + s]); __syncthreads(); }
        if (tid == 0) g_h0[b * 2048 + o] = red[0];
        __syncthreads();
        red[tid] = sm; __syncthreads();
        for (int s = 128; s > 0; s >>= 1) { if (tid < s) red[tid] += red[tid + s]; __syncthreads(); }
        if (tid == 0) g_h0[b * 2048 + 1024 + o] = red[0] * (1.0f / 1024.0f);
        __syncthreads();
    }
}

// ---------------- MLP head ----------------
__global__ void mlp_bn_kernel(const float* __restrict__ w, const float* __restrict__ bnp,
                              const float* __restrict__ hin, float* __restrict__ hout,
                              int IN, int ON) {
    const int b = blockIdx.x, o = threadIdx.x;
    const float* hr = hin + (size_t)b * IN;
    const float* wr = w + (size_t)o * IN;
    float acc = 0.f;
    for (int c = 0; c < IN; c++) acc = fmaf(hr[c], wr[c], acc);
    float gg = bnp[o], bb = bnp[ON + o], mm = bnp[2 * ON + o], vv = bnp[3 * ON + o];
    float scale = gg / sqrtf(vv + CEPS);
    float y = (acc - mm) * scale + bb;
    hout[(size_t)b * ON + o] = (y > 0.f) ? y : CSLOPE * y;
}

__global__ void final_kernel(const float* __restrict__ w, const float* __restrict__ bias,
                             float* __restrict__ out) {
    const int b = blockIdx.x, o = threadIdx.x;
    const float* hr = g_h2 + b * 256;
    const float* wr = w + (size_t)o * 256;
    float acc = bias[o];
    for (int c = 0; c < 256; c++) acc = fmaf(hr[c], wr[c], acc);
    out[b * 64 + o] = acc;
}

// ---------------- launch ----------------
extern "C" void kernel_launch(void* const* d_in, const int* in_sizes, int n_in,
                              void* d_out, int out_size) {
    const float* x    = (const float*)d_in[0];
    const float* w0   = (const float*)d_in[1];
    const float* w1   = (const float*)d_in[2];
    const float* w2   = (const float*)d_in[3];
    const float* w3   = (const float*)d_in[4];
    const float* bn0  = (const float*)d_in[5];
    const float* bn1  = (const float*)d_in[6];
    const float* bn2  = (const float*)d_in[7];
    const float* bn3  = (const float*)d_in[8];
    const float* we   = (const float*)d_in[9];
    const float* bne  = (const float*)d_in[10];
    const float* wf0  = (const float*)d_in[11];
    const float* bnf0 = (const float*)d_in[12];
    const float* wf1  = (const float*)d_in[13];
    const float* bnf1 = (const float*)d_in[14];
    const float* wfin = (const float*)d_in[15];
    const float* bfin = (const float*)d_in[16];

    float *h0, *h1, *h2;
    cudaGetSymbolAddress((void**)&h0, g_h0);
    cudaGetSymbolAddress((void**)&h1, g_h1);
    cudaGetSymbolAddress((void**)&h2, g_h2);

    dim3 gpn(NPTS, BATCH);

    // block 1: input x (C=3) -> x1 (64) at cat[0:64]
    knn_kernel<3><<<gpn, 256>>>(x, 0);
    conv_kernel<3, 64><<<gpn, 64>>>(x, w0, bn0, 0, 0);
    // block 2: x1 (C=64) -> x2 (64) at cat[64:128]
    knn_kernel<64><<<gpn, 256>>>(nullptr, 0);
    conv_kernel<64, 64><<<gpn, 64>>>(nullptr, w1, bn1, 0, 64);
    // block 3: x2 (C=64) -> x3 (128) at cat[128:256]
    knn_kernel<64><<<gpn, 256>>>(nullptr, 64);
    conv_kernel<64, 128><<<gpn, 128>>>(nullptr, w2, bn2, 64, 128);
    // block 4: x3 (C=128) -> x4 (256) at cat[256:512]
    knn_kernel<128><<<gpn, 256>>>(nullptr, 128);
    conv_kernel<128, 256><<<gpn, 256>>>(nullptr, w3, bn3, 128, 256);
    // embedding + global pools -> h0 (B, 2048)
    edge_kernel<<<dim3(128, BATCH), 256>>>(we, bne);
    // MLP head
    mlp_bn_kernel<<<BATCH, 512>>>(wf0, bnf0, h0, h1, 2048, 512);
    mlp_bn_kernel<<<BATCH, 256>>>(wf1, bnf1, h1, h2, 512, 256);
    final_kernel<<<BATCH, 64>>>(wfin, bfin, (float*)d_out);
}

// round 3
// speedup vs baseline: 4.6834x; 4.6834x over previous
#include <cuda_runtime.h>
#include <math.h>

#define NPTS 1024
#define KNB 20
#define BATCH 8
#define CEPS 1e-5f
#define CSLOPE 0.2f

// ---------------- scratch (no allocations allowed) ----------------
__device__ float g_cat[(size_t)BATCH * 512 * NPTS];   // x1(0:64) x2(64:128) x3(128:256) x4(256:512)
__device__ float g_gram[(size_t)BATCH * NPTS * NPTS]; // per-layer Gram matrix (reused)
__device__ float g_xx[BATCH * NPTS];
__device__ int   g_idx[(size_t)BATCH * NPTS * KNB];
__device__ float g_h0[BATCH * 2048];
__device__ float g_h1[BATCH * 512];
__device__ float g_h2[BATCH * 256];
// packed transposed weights: wn[c4][o] = float4 of w[o][4c4..4c4+3], wd = w[o][C+c]-w[o][c]
__device__ float g_w1n[1  * 64  * 4], g_w1d[1  * 64  * 4];
__device__ float g_w2n[16 * 64  * 4], g_w2d[16 * 64  * 4];
__device__ float g_w3n[16 * 128 * 4], g_w3d[16 * 128 * 4];
__device__ float g_w4n[32 * 256 * 4], g_w4d[32 * 256 * 4];

// ---------------- weight transpose/pack ----------------
__global__ void prep_kernel(const float* __restrict__ w, float* __restrict__ wn,
                            float* __restrict__ wd, int C, int O) {
    int idx = blockIdx.x * 256 + threadIdx.x;
    int C4 = (C + 3) / 4, CP = C4 * 4;
    if (idx >= O * CP) return;
    int o = idx / CP, cp = idx - o * CP;
    float a = (cp < C) ? w[o * 2 * C + cp] : 0.f;
    float b = (cp < C) ? (w[o * 2 * C + C + cp] - a) : 0.f;
    int dst = (cp / 4) * O * 4 + o * 4 + (cp & 3);
    wn[dst] = a;
    wd[dst] = b;
}

// ---------------- xx[m] = ||x_m||^2 (coalesced over m) ----------------
template<int C>
__global__ void xx_kernel(const float* __restrict__ xin, int cin_off) {
    const int b = blockIdx.y;
    const int m = blockIdx.x * 256 + threadIdx.x;
    const float* xb = xin ? (xin + (size_t)b * C * NPTS)
                          : (g_cat + (size_t)b * 512 * NPTS + (size_t)cin_off * NPTS);
    float s = 0.f;
    #pragma unroll 8
    for (int c = 0; c < C; c++) {
        float v = xb[(size_t)c * NPTS + m];
        s = fmaf(v, v, s);
    }
    g_xx[b * NPTS + m] = s;
}

// ---------------- Gram matrix G[b][n][m] = sum_c x[c][n] x[c][m] ----------------
// 128x128 tile per block, 256 threads, 8x8 register tile per thread.
template<int C>
__global__ void __launch_bounds__(256) gram_kernel(const float* __restrict__ xin, int cin_off) {
    const int b = blockIdx.z;
    const int m0 = blockIdx.x * 128, n0 = blockIdx.y * 128;
    const float* xb = xin ? (xin + (size_t)b * C * NPTS)
                          : (g_cat + (size_t)b * 512 * NPTS + (size_t)cin_off * NPTS);
    __shared__ __align__(16) float As[8][128];
    __shared__ __align__(16) float Bs[8][128];
    const int tid = threadIdx.x;
    const int tx = tid & 15, ty = tid >> 4;

    float acc[8][8];
    #pragma unroll
    for (int i = 0; i < 8; i++)
        #pragma unroll
        for (int j = 0; j < 8; j++) acc[i][j] = 0.f;

    const int NCH = (C + 7) / 8;
    for (int ch = 0; ch < NCH; ch++) {
        const int c0 = ch * 8;
        #pragma unroll
        for (int i = 0; i < 4; i++) {
            int idx = tid + i * 256;
            int r = idx >> 7, col = idx & 127;
            int c = c0 + r;
            As[r][col] = (c < C) ? xb[(size_t)c * NPTS + n0 + col] : 0.f;
            Bs[r][col] = (c < C) ? xb[(size_t)c * NPTS + m0 + col] : 0.f;
        }
        __syncthreads();
        #pragma unroll
        for (int r = 0; r < 8; r++) {
            float4 a0 = *(const float4*)&As[r][ty * 8];
            float4 a1 = *(const float4*)&As[r][ty * 8 + 4];
            float4 b0 = *(const float4*)&Bs[r][tx * 8];
            float4 b1 = *(const float4*)&Bs[r][tx * 8 + 4];
            float av[8] = {a0.x, a0.y, a0.z, a0.w, a1.x, a1.y, a1.z, a1.w};
            float bv[8] = {b0.x, b0.y, b0.z, b0.w, b1.x, b1.y, b1.z, b1.w};
            #pragma unroll
            for (int i = 0; i < 8; i++)
                #pragma unroll
                for (int j = 0; j < 8; j++)
                    acc[i][j] = fmaf(av[i], bv[j], acc[i][j]);
        }
        __syncthreads();
    }

    #pragma unroll
    for (int i = 0; i < 8; i++) {
        float* Gr = g_gram + ((size_t)b * NPTS + n0 + ty * 8 + i) * NPTS + m0 + tx * 8;
        *(float4*)Gr       = make_float4(acc[i][0], acc[i][1], acc[i][2], acc[i][3]);
        *(float4*)(Gr + 4) = make_float4(acc[i][4], acc[i][5], acc[i][6], acc[i][7]);
    }
}

// ---------------- top-20 selection: one warp per (b, n), distances in registers ----------------
// score s[m] = 2*G[n][m] - xx[m]  (xx[n] constant per row -> same ranking as reference pd)
__global__ void __launch_bounds__(256) topk_kernel() {
    const int tid = threadIdx.x;
    const int lane = tid & 31;
    const int gw = blockIdx.x * 8 + (tid >> 5);
    const int b = gw >> 10, n = gw & 1023;

    const float* Grow = g_gram + ((size_t)b * NPTS + n) * NPTS;
    const float* xxb = g_xx + b * NPTS;

    float d[32];
    #pragma unroll
    for (int j = 0; j < 32; j++) {
        int m = j * 32 + lane;
        d[j] = 2.f * Grow[m] - xxb[m];
    }

    int* myidx = g_idx + ((size_t)b * NPTS + n) * KNB;
    for (int k = 0; k < KNB; k++) {
        float bv = -INFINITY; int bj = 0;
        #pragma unroll
        for (int j = 0; j < 32; j++) {
            if (d[j] > bv) { bv = d[j]; bj = j; }  // ascending j -> lowest index on ties
        }
        int bidx = bj * 32 + lane;
        #pragma unroll
        for (int off = 16; off > 0; off >>= 1) {
            float ov = __shfl_xor_sync(0xffffffffu, bv, off);
            int   oi = __shfl_xor_sync(0xffffffffu, bidx, off);
            if (ov > bv || (ov == bv && oi < bidx)) { bv = ov; bidx = oi; }
        }
        if (lane == (bidx & 31)) {
            int jj = bidx >> 5;
            #pragma unroll
            for (int j = 0; j < 32; j++)
                if (j == jj) d[j] = -INFINITY;
        }
        if (lane == 0) myidx[k] = bidx;
    }
}

// ---------------- edge conv block ----------------
// y[o,k] = sum_c w[o,c]*nbr[k][c] + sum_c (w[o,C+c]-w[o,c])*ctr[c]; BN+lrelu+max over k.
// Weights come pre-transposed/packed: coalesced float4 loads.
template<int CIN, int O>
__global__ void __launch_bounds__(O) conv_kernel(const float* __restrict__ xin,
                                                 const float* __restrict__ w4T,
                                                 const float* __restrict__ d4T,
                                                 const float* __restrict__ bnp,
                                                 int cin_off, int cout_off) {
    constexpr int C4 = (CIN + 3) / 4;
    constexpr int CP = C4 * 4;
    const int b = blockIdx.y, n = blockIdx.x, tid = threadIdx.x;
    const float* xb = xin ? (xin + (size_t)b * CIN * NPTS)
                          : (g_cat + (size_t)b * 512 * NPTS + (size_t)cin_off * NPTS);
    __shared__ __align__(16) float ctr[CP];
    __shared__ __align__(16) float nbr[KNB][CP];
    __shared__ int jid[KNB];

    for (int c = tid; c < CP; c += O) ctr[c] = (c < CIN) ? xb[(size_t)c * NPTS + n] : 0.f;
    if (tid < KNB) jid[tid] = g_idx[((size_t)b * NPTS + n) * KNB + tid];
    __syncthreads();
    for (int t = tid; t < KNB * CP; t += O) {
        int k = t / CP, c = t - k * CP;
        nbr[k][c] = (c < CIN) ? xb[(size_t)c * NPTS + jid[k]] : 0.f;
    }
    __syncthreads();

    const int o = tid;
    const float4* w4 = (const float4*)w4T;
    const float4* dd4 = (const float4*)d4T;

    float base = 0.f;
    #pragma unroll
    for (int c4 = 0; c4 < C4; c4++) {
        float4 dv = dd4[c4 * O + o];
        float4 cv = *(const float4*)&ctr[c4 * 4];
        base = fmaf(dv.x, cv.x, base);
        base = fmaf(dv.y, cv.y, base);
        base = fmaf(dv.z, cv.z, base);
        base = fmaf(dv.w, cv.w, base);
    }

    float acc[KNB];
    #pragma unroll
    for (int k = 0; k < KNB; k++) acc[k] = base;

    float4 wv = w4[o];
    #pragma unroll 1
    for (int c4 = 0; c4 < C4; c4++) {
        float4 wnext = (c4 + 1 < C4) ? w4[(c4 + 1) * O + o] : wv;
        #pragma unroll
        for (int k = 0; k < KNB; k++) {
            float4 nv = *(const float4*)&nbr[k][c4 * 4];
            acc[k] = fmaf(wv.x, nv.x, acc[k]);
            acc[k] = fmaf(wv.y, nv.y, acc[k]);
            acc[k] = fmaf(wv.z, nv.z, acc[k]);
            acc[k] = fmaf(wv.w, nv.w, acc[k]);
        }
        wv = wnext;
    }

    float gg = bnp[o], bb = bnp[O + o], mm = bnp[2 * O + o], vv = bnp[3 * O + o];
    float scale = gg / sqrtf(vv + CEPS);
    float best = -INFINITY;
    #pragma unroll
    for (int k = 0; k < KNB; k++) {
        float y = (acc[k] - mm) * scale + bb;
        y = (y > 0.f) ? y : CSLOPE * y;
        best = fmaxf(best, y);
    }
    g_cat[(size_t)b * 512 * NPTS + (size_t)(cout_off + o) * NPTS + n] = best;
}

// ---------------- embedding (cat[512] -> 1024) + BN + lrelu + max/mean pools ----------------
__global__ void __launch_bounds__(256) edge_kernel(const float* __restrict__ we,
                                                   const float* __restrict__ bne) {
    const int b = blockIdx.y, tid = threadIdx.x;
    const int o0 = blockIdx.x * 8;
    const int lane = tid & 31, wid = tid >> 5;
    __shared__ __align__(16) float ws[8][512];
    for (int t = tid; t < 8 * 512; t += 256)
        ws[t >> 9][t & 511] = we[(size_t)(o0 + (t >> 9)) * 512 + (t & 511)];
    __syncthreads();

    const float* catb = g_cat + (size_t)b * 512 * NPTS;
    const int n0 = tid * 4;

    float acc[8][4];
    #pragma unroll
    for (int j = 0; j < 8; j++)
        acc[j][0] = acc[j][1] = acc[j][2] = acc[j][3] = 0.f;

    #pragma unroll 1
    for (int c = 0; c < 512; c += 4) {
        float4 x0 = *(const float4*)(catb + (size_t)c * NPTS + n0);
        float4 x1 = *(const float4*)(catb + (size_t)(c + 1) * NPTS + n0);
        float4 x2 = *(const float4*)(catb + (size_t)(c + 2) * NPTS + n0);
        float4 x3 = *(const float4*)(catb + (size_t)(c + 3) * NPTS + n0);
        #pragma unroll
        for (int j = 0; j < 8; j++) {
            float4 wv = *(const float4*)&ws[j][c];
            acc[j][0] = fmaf(wv.x, x0.x, acc[j][0]);
            acc[j][1] = fmaf(wv.x, x0.y, acc[j][1]);
            acc[j][2] = fmaf(wv.x, x0.z, acc[j][2]);
            acc[j][3] = fmaf(wv.x, x0.w, acc[j][3]);
            acc[j][0] = fmaf(wv.y, x1.x, acc[j][0]);
            acc[j][1] = fmaf(wv.y, x1.y, acc[j][1]);
            acc[j][2] = fmaf(wv.y, x1.z, acc[j][2]);
            acc[j][3] = fmaf(wv.y, x1.w, acc[j][3]);
            acc[j][0] = fmaf(wv.z, x2.x, acc[j][0]);
            acc[j][1] = fmaf(wv.z, x2.y, acc[j][1]);
            acc[j][2] = fmaf(wv.z, x2.z, acc[j][2]);
            acc[j][3] = fmaf(wv.z, x2.w, acc[j][3]);
            acc[j][0] = fmaf(wv.w, x3.x, acc[j][0]);
            acc[j][1] = fmaf(wv.w, x3.y, acc[j][1]);
            acc[j][2] = fmaf(wv.w, x3.z, acc[j][2]);
            acc[j][3] = fmaf(wv.w, x3.w, acc[j][3]);
        }
    }

    __shared__ float wmax[8], wsum[8];
    #pragma unroll 1
    for (int j = 0; j < 8; j++) {
        const int o = o0 + j;
        float gg = bne[o], bb = bne[1024 + o], mm = bne[2048 + o], vv = bne[3072 + o];
        float scale = gg / sqrtf(vv + CEPS);
        float mx = -INFINITY, sm = 0.f;
        #pragma unroll
        for (int q = 0; q < 4; q++) {
            float y = (acc[j][q] - mm) * scale + bb;
            y = (y > 0.f) ? y : CSLOPE * y;
            mx = fmaxf(mx, y);
            sm += y;
        }
        #pragma unroll
        for (int off = 16; off > 0; off >>= 1) {
            mx = fmaxf(mx, __shfl_xor_sync(0xffffffffu, mx, off));
            sm += __shfl_xor_sync(0xffffffffu, sm, off);
        }
        if (lane == 0) { wmax[wid] = mx; wsum[wid] = sm; }
        __syncthreads();
        if (tid == 0) {
            float m2 = -INFINITY, s2 = 0.f;
            #pragma unroll
            for (int w = 0; w < 8; w++) { m2 = fmaxf(m2, wmax[w]); s2 += wsum[w]; }
            g_h0[b * 2048 + o] = m2;
            g_h0[b * 2048 + 1024 + o] = s2 * (1.0f / 1024.0f);
        }
        __syncthreads();
    }
}

// ---------------- MLP head ----------------
__global__ void mlp_bn_kernel(const float* __restrict__ w, const float* __restrict__ bnp,
                              const float* __restrict__ hin, float* __restrict__ hout,
                              int IN, int ON) {
    const int b = blockIdx.x, o = threadIdx.x;
    const float* hr = hin + (size_t)b * IN;
    const float* wr = w + (size_t)o * IN;
    float a0 = 0.f, a1 = 0.f, a2 = 0.f, a3 = 0.f;
    for (int c = 0; c < IN; c += 4) {
        a0 = fmaf(hr[c],     wr[c],     a0);
        a1 = fmaf(hr[c + 1], wr[c + 1], a1);
        a2 = fmaf(hr[c + 2], wr[c + 2], a2);
        a3 = fmaf(hr[c + 3], wr[c + 3], a3);
    }
    float acc = (a0 + a1) + (a2 + a3);
    float gg = bnp[o], bb = bnp[ON + o], mm = bnp[2 * ON + o], vv = bnp[3 * ON + o];
    float scale = gg / sqrtf(vv + CEPS);
    float y = (acc - mm) * scale + bb;
    hout[(size_t)b * ON + o] = (y > 0.f) ? y : CSLOPE * y;
}

__global__ void final_kernel(const float* __restrict__ w, const float* __restrict__ bias,
                             float* __restrict__ out) {
    const int b = blockIdx.x, o = threadIdx.x;
    const float* hr = g_h2 + b * 256;
    const float* wr = w + (size_t)o * 256;
    float a0 = 0.f, a1 = 0.f, a2 = 0.f, a3 = 0.f;
    for (int c = 0; c < 256; c += 4) {
        a0 = fmaf(hr[c],     wr[c],     a0);
        a1 = fmaf(hr[c + 1], wr[c + 1], a1);
        a2 = fmaf(hr[c + 2], wr[c + 2], a2);
        a3 = fmaf(hr[c + 3], wr[c + 3], a3);
    }
    out[b * 64 + o] = bias[o] + (a0 + a1) + (a2 + a3);
}

// ---------------- launch ----------------
extern "C" void kernel_launch(void* const* d_in, const int* in_sizes, int n_in,
                              void* d_out, int out_size) {
    const float* x    = (const float*)d_in[0];
    const float* w0   = (const float*)d_in[1];
    const float* w1   = (const float*)d_in[2];
    const float* w2   = (const float*)d_in[3];
    const float* w3   = (const float*)d_in[4];
    const float* bn0  = (const float*)d_in[5];
    const float* bn1  = (const float*)d_in[6];
    const float* bn2  = (const float*)d_in[7];
    const float* bn3  = (const float*)d_in[8];
    const float* we   = (const float*)d_in[9];
    const float* bne  = (const float*)d_in[10];
    const float* wf0  = (const float*)d_in[11];
    const float* bnf0 = (const float*)d_in[12];
    const float* wf1  = (const float*)d_in[13];
    const float* bnf1 = (const float*)d_in[14];
    const float* wfin = (const float*)d_in[15];
    const float* bfin = (const float*)d_in[16];

    float *h0, *h1, *h2;
    cudaGetSymbolAddress((void**)&h0, g_h0);
    cudaGetSymbolAddress((void**)&h1, g_h1);
    cudaGetSymbolAddress((void**)&h2, g_h2);
    float *w1n, *w1d, *w2n, *w2d, *w3n, *w3d, *w4n, *w4d;
    cudaGetSymbolAddress((void**)&w1n, g_w1n); cudaGetSymbolAddress((void**)&w1d, g_w1d);
    cudaGetSymbolAddress((void**)&w2n, g_w2n); cudaGetSymbolAddress((void**)&w2d, g_w2d);
    cudaGetSymbolAddress((void**)&w3n, g_w3n); cudaGetSymbolAddress((void**)&w3d, g_w3d);
    cudaGetSymbolAddress((void**)&w4n, g_w4n); cudaGetSymbolAddress((void**)&w4d, g_w4d);

    // pack/transpose conv weights
    prep_kernel<<<1,   256>>>(w0, w1n, w1d, 3,   64);
    prep_kernel<<<16,  256>>>(w1, w2n, w2d, 64,  64);
    prep_kernel<<<32,  256>>>(w2, w3n, w3d, 64,  128);
    prep_kernel<<<128, 256>>>(w3, w4n, w4d, 128, 256);

    dim3 gpn(NPTS, BATCH);
    dim3 gxx(NPTS / 256, BATCH);
    dim3 ggr(8, 8, BATCH);

    // block 1: input x (C=3) -> x1 (64) at cat[0:64]
    xx_kernel<3><<<gxx, 256>>>(x, 0);
    gram_kernel<3><<<ggr, 256>>>(x, 0);
    topk_kernel<<<1024, 256>>>();
    conv_kernel<3, 64><<<gpn, 64>>>(x, w1n, w1d, bn0, 0, 0);
    // block 2: x1 (C=64) -> x2 (64) at cat[64:128]
    xx_kernel<64><<<gxx, 256>>>(nullptr, 0);
    gram_kernel<64><<<ggr, 256>>>(nullptr, 0);
    topk_kernel<<<1024, 256>>>();
    conv_kernel<64, 64><<<gpn, 64>>>(nullptr, w2n, w2d, bn1, 0, 64);
    // block 3: x2 (C=64) -> x3 (128) at cat[128:256]
    xx_kernel<64><<<gxx, 256>>>(nullptr, 64);
    gram_kernel<64><<<ggr, 256>>>(nullptr, 64);
    topk_kernel<<<1024, 256>>>();
    conv_kernel<64, 128><<<gpn, 128>>>(nullptr, w3n, w3d, bn2, 64, 128);
    // block 4: x3 (C=128) -> x4 (256) at cat[256:512]
    xx_kernel<128><<<gxx, 256>>>(nullptr, 128);
    gram_kernel<128><<<ggr, 256>>>(nullptr, 128);
    topk_kernel<<<1024, 256>>>();
    conv_kernel<128, 256><<<gpn, 256>>>(nullptr, w4n, w4d, bn3, 128, 256);
    // embedding + global pools -> h0 (B, 2048)
    edge_kernel<<<dim3(128, BATCH), 256>>>(we, bne);
    // MLP head
    mlp_bn_kernel<<<BATCH, 512>>>(wf0, bnf0, h0, h1, 2048, 512);
    mlp_bn_kernel<<<BATCH, 256>>>(wf1, bnf1, h1, h2, 512, 256);
    final_kernel<<<BATCH, 64>>>(wfin, bfin, (float*)d_out);
}

// round 4
// speedup vs baseline: 5.6485x; 1.2061x over previous
#include <cuda_runtime.h>
#include <math.h>
#include <stdint.h>

#define NPTS 1024
#define KNB 20
#define BATCH 8
#define CEPS 1e-5f
#define CSLOPE 0.2f
#define MTOT (BATCH * NPTS * KNB)   // 163840 edge-feature rows

// ---------------- scratch (no allocations allowed) ----------------
__device__ float g_cat[(size_t)BATCH * 512 * NPTS];   // x1(0:64) x2(64:128) x3(128:256) x4(256:512)
__device__ float g_gram[(size_t)BATCH * NPTS * NPTS]; // gram; later reused as edge activations e[b][o][n]
__device__ float g_xx[BATCH * NPTS];
__device__ int   g_idx[(size_t)BATCH * NPTS * KNB];
__device__ float g_xT[(size_t)BATCH * NPTS * 128];    // transposed features [b][n][c]
__device__ float g_F[(size_t)MTOT * 256];             // edge-feature GEMM A
__device__ float g_Y[(size_t)MTOT * 256];             // GEMM output (pre-pool)
__device__ float g_Wt[256 * 256];                     // transposed weights [c'][o]
__device__ float g_h0[BATCH * 2048];
__device__ float g_h1[BATCH * 512];
__device__ float g_h2[BATCH * 256];

// ================= tf32 MMA helpers =================
__device__ __forceinline__ uint32_t f2tf(float f) {
    uint32_t u; asm("cvt.rna.tf32.f32 %0, %1;" : "=r"(u) : "f"(f)); return u;
}
__device__ __forceinline__ void mma8(float* c, const uint32_t* a, const uint32_t* b) {
    asm volatile(
        "mma.sync.aligned.m16n8k8.row.col.f32.tf32.tf32.f32 "
        "{%0,%1,%2,%3}, {%4,%5,%6,%7}, {%8,%9}, {%0,%1,%2,%3};\n"
        : "+f"(c[0]), "+f"(c[1]), "+f"(c[2]), "+f"(c[3])
        : "r"(a[0]), "r"(a[1]), "r"(a[2]), "r"(a[3]), "r"(b[0]), "r"(b[1]));
}

// ================= generic tf32 GEMM =================
// C[M][N] = A[M][K] (row-major) x B[K][N] (row-major). 128 x TN block tile,
// 8 warps (2x4), KC=32 k-chunk, register-staged prefetch, tf32-rounded smem.
template<int TN>
__global__ void __launch_bounds__(256, 1) gemm_tf32(
    const float* __restrict__ A, const float* __restrict__ B, float* __restrict__ Cc,
    int K, int lda, int ldb, int ldc,
    size_t sAz, size_t sBz, size_t sCz)
{
    constexpr int KC = 32;
    constexpr int NT = TN / 32;       // n mma-tiles per warp
    constexpr int NF4B = TN / 32;     // B float4 loads per thread

    const int z = blockIdx.z;
    const int m0 = blockIdx.y * 128, n0 = blockIdx.x * TN;
    const float* Ab = A + z * sAz + (size_t)m0 * lda;
    const float* Bb = B + z * sBz + n0;
    float* Cb = Cc + z * sCz;

    __shared__ uint32_t As[128][KC + 4];
    __shared__ uint32_t Bs[KC][TN + 4];

    const int tid = threadIdx.x, lane = tid & 31, wrp = tid >> 5;
    const int wm = wrp >> 2, wn = wrp & 3;
    const int qr = lane >> 2, qc = lane & 3;

    float acc[4][NT][4];
    #pragma unroll
    for (int i = 0; i < 4; i++)
        #pragma unroll
        for (int j = 0; j < NT; j++)
            #pragma unroll
            for (int q = 0; q < 4; q++) acc[i][j][q] = 0.f;

    int ar[4], ac[4];
    #pragma unroll
    for (int i = 0; i < 4; i++) { int idx = tid + i * 256; ar[i] = idx >> 3; ac[i] = (idx & 7) * 4; }
    int br[NF4B], bc[NF4B];
    #pragma unroll
    for (int i = 0; i < NF4B; i++) { int idx = tid + i * 256; br[i] = idx / (TN / 4); bc[i] = (idx % (TN / 4)) * 4; }

    float4 ra[4], rb[NF4B];
    #pragma unroll
    for (int i = 0; i < 4; i++) ra[i] = *(const float4*)(Ab + (size_t)ar[i] * lda + ac[i]);
    #pragma unroll
    for (int i = 0; i < NF4B; i++) rb[i] = *(const float4*)(Bb + (size_t)br[i] * ldb + bc[i]);

    const int KT = K / KC;
    for (int kt = 0; kt < KT; kt++) {
        #pragma unroll
        for (int i = 0; i < 4; i++) {
            As[ar[i]][ac[i]    ] = f2tf(ra[i].x);
            As[ar[i]][ac[i] + 1] = f2tf(ra[i].y);
            As[ar[i]][ac[i] + 2] = f2tf(ra[i].z);
            As[ar[i]][ac[i] + 3] = f2tf(ra[i].w);
        }
        #pragma unroll
        for (int i = 0; i < NF4B; i++) {
            Bs[br[i]][bc[i]    ] = f2tf(rb[i].x);
            Bs[br[i]][bc[i] + 1] = f2tf(rb[i].y);
            Bs[br[i]][bc[i] + 2] = f2tf(rb[i].z);
            Bs[br[i]][bc[i] + 3] = f2tf(rb[i].w);
        }
        __syncthreads();
        if (kt + 1 < KT) {
            const float* An = Ab + (kt + 1) * KC;
            const float* Bn = Bb + (size_t)(kt + 1) * KC * ldb;
            #pragma unroll
            for (int i = 0; i < 4; i++) ra[i] = *(const float4*)(An + (size_t)ar[i] * lda + ac[i]);
            #pragma unroll
            for (int i = 0; i < NF4B; i++) rb[i] = *(const float4*)(Bn + (size_t)br[i] * ldb + bc[i]);
        }
        #pragma unroll
        for (int kk = 0; kk < 4; kk++) {
            uint32_t af[4][4];
            #pragma unroll
            for (int mt = 0; mt < 4; mt++) {
                int r = wm * 64 + mt * 16 + qr, c = kk * 8 + qc;
                af[mt][0] = As[r][c];     af[mt][1] = As[r + 8][c];
                af[mt][2] = As[r][c + 4]; af[mt][3] = As[r + 8][c + 4];
            }
            uint32_t bf[NT][2];
            #pragma unroll
            for (int nt = 0; nt < NT; nt++) {
                int cc = wn * (TN / 4) + nt * 8 + qr, rr = kk * 8 + qc;
                bf[nt][0] = Bs[rr][cc]; bf[nt][1] = Bs[rr + 4][cc];
            }
            #pragma unroll
            for (int mt = 0; mt < 4; mt++)
                #pragma unroll
                for (int nt = 0; nt < NT; nt++)
                    mma8(acc[mt][nt], af[mt], bf[nt]);
        }
        __syncthreads();
    }

    #pragma unroll
    for (int mt = 0; mt < 4; mt++) {
        #pragma unroll
        for (int nt = 0; nt < NT; nt++) {
            int r = m0 + wm * 64 + mt * 16 + qr;
            int cc = n0 + wn * (TN / 4) + nt * 8 + 2 * qc;
            *(float2*)(Cb + (size_t)r * ldc + cc)       = make_float2(acc[mt][nt][0], acc[mt][nt][1]);
            *(float2*)(Cb + (size_t)(r + 8) * ldc + cc) = make_float2(acc[mt][nt][2], acc[mt][nt][3]);
        }
    }
}

// ================= support kernels =================

// transpose xb[c][n] -> g_xT[b][n][c] (ld = ldT)
__global__ void transpose_kernel(const float* __restrict__ xin, int cin_off, int C, int ldT) {
    const int b = blockIdx.z;
    const float* xb = xin ? (xin + (size_t)b * C * NPTS)
                          : (g_cat + (size_t)b * 512 * NPTS + (size_t)cin_off * NPTS);
    __shared__ float t[32][33];
    const int n0 = blockIdx.x * 32, c0 = blockIdx.y * 32;
    const int tx = threadIdx.x, ty = threadIdx.y;
    #pragma unroll
    for (int i = 0; i < 32; i += 8) {
        int c = c0 + ty + i;
        if (c < C) t[ty + i][tx] = xb[(size_t)c * NPTS + n0 + tx];
    }
    __syncthreads();
    #pragma unroll
    for (int i = 0; i < 32; i += 8) {
        int n = n0 + ty + i, c = c0 + tx;
        if (c < C) g_xT[((size_t)b * NPTS + n) * ldT + c] = t[tx][ty + i];
    }
}

// build F rows: m = (b*NPTS+n)*KNB + kk; cols [0:C)=nb-ctr, [C:2C)=ctr, rest 0
__global__ void fbuild_kernel(int C, int KP, int ldT) {
    const int b = blockIdx.y, n = blockIdx.x, tid = threadIdx.x;
    const float* xTb = g_xT + (size_t)b * NPTS * ldT;
    __shared__ int jid[KNB];
    if (tid < KNB) jid[tid] = g_idx[((size_t)b * NPTS + n) * KNB + tid];
    __syncthreads();
    const size_t m0 = ((size_t)b * NPTS + n) * KNB;
    if (C % 4 == 0) {
        const int C4 = C / 4;
        const int tot = KNB * C4;
        for (int t = tid; t < tot; t += 256) {
            int kk = t / C4, c4 = t - kk * C4;
            float4 ct = *(const float4*)(xTb + (size_t)n * ldT + c4 * 4);
            float4 nb = *(const float4*)(xTb + (size_t)jid[kk] * ldT + c4 * 4);
            float* Fr = g_F + (m0 + kk) * KP;
            ((float4*)Fr)[c4] = make_float4(nb.x - ct.x, nb.y - ct.y, nb.z - ct.z, nb.w - ct.w);
            ((float4*)(Fr + C))[c4] = ct;
        }
    } else { // C == 3, KP == 32
        for (int t = tid; t < KNB * 32; t += 256) {
            int kk = t / 32, c = t - kk * 32;
            float v = 0.f;
            if (c < 3)      v = xTb[(size_t)jid[kk] * ldT + c] - xTb[(size_t)n * ldT + c];
            else if (c < 6) v = xTb[(size_t)n * ldT + (c - 3)];
            g_F[(m0 + kk) * 32 + c] = v;
        }
    }
}

// Wt[kp][o] = w[o][kp] (zero pad for kp >= 2C)
__global__ void wprep_kernel(const float* __restrict__ w, int C2, int KP, int O) {
    int i = blockIdx.x * 256 + threadIdx.x;
    if (i >= KP * O) return;
    int kp = i / O, o = i - kp * O;
    g_Wt[i] = (kp < C2) ? w[(size_t)o * C2 + kp] : 0.f;
}

// conv epilogue: max over KNB, then BN (gamma>0 => monotone) + lrelu
__global__ void cepi_kernel(const float* __restrict__ bnp, int O, int cout_off) {
    const int b = blockIdx.y, n = blockIdx.x, o = threadIdx.x;
    const size_t base = ((size_t)b * NPTS + n) * KNB;
    const float* Yp = g_Y + base * O + o;
    float mx = -INFINITY;
    #pragma unroll
    for (int k = 0; k < KNB; k++) mx = fmaxf(mx, Yp[(size_t)k * O]);
    float gg = bnp[o], bb = bnp[O + o], mm = bnp[2 * O + o], vv = bnp[3 * O + o];
    float scale = gg / sqrtf(vv + CEPS);
    float y = (mx - mm) * scale + bb;
    y = (y > 0.f) ? y : CSLOPE * y;
    g_cat[(size_t)b * 512 * NPTS + (size_t)(cout_off + o) * NPTS + n] = y;
}

// edge pool: e[b][o][n] raw in g_gram -> BN + lrelu -> max & mean over n
__global__ void epool_kernel(const float* __restrict__ bne) {
    const int b = blockIdx.y;
    const int w = threadIdx.x >> 5, lane = threadIdx.x & 31;
    const int o = blockIdx.x * 8 + w;
    const float* er = g_gram + ((size_t)b * 1024 + o) * NPTS;
    float gg = bne[o], bb = bne[1024 + o], mm = bne[2048 + o], vv = bne[3072 + o];
    float scale = gg / sqrtf(vv + CEPS);
    float mx = -INFINITY, sm = 0.f;
    for (int i = lane; i < NPTS; i += 32) {
        float y = (er[i] - mm) * scale + bb;
        y = (y > 0.f) ? y : CSLOPE * y;
        mx = fmaxf(mx, y);
        sm += y;
    }
    #pragma unroll
    for (int off = 16; off > 0; off >>= 1) {
        mx = fmaxf(mx, __shfl_xor_sync(0xffffffffu, mx, off));
        sm += __shfl_xor_sync(0xffffffffu, sm, off);
    }
    if (lane == 0) {
        g_h0[b * 2048 + o] = mx;
        g_h0[b * 2048 + 1024 + o] = sm * (1.0f / 1024.0f);
    }
}

// ================= exact fp32 kNN path (unchanged) =================
template<int C>
__global__ void xx_kernel(const float* __restrict__ xin, int cin_off) {
    const int b = blockIdx.y;
    const int m = blockIdx.x * 256 + threadIdx.x;
    const float* xb = xin ? (xin + (size_t)b * C * NPTS)
                          : (g_cat + (size_t)b * 512 * NPTS + (size_t)cin_off * NPTS);
    float s = 0.f;
    #pragma unroll 8
    for (int c = 0; c < C; c++) {
        float v = xb[(size_t)c * NPTS + m];
        s = fmaf(v, v, s);
    }
    g_xx[b * NPTS + m] = s;
}

template<int C>
__global__ void __launch_bounds__(256) gram_kernel(const float* __restrict__ xin, int cin_off) {
    const int b = blockIdx.z;
    const int m0 = blockIdx.x * 128, n0 = blockIdx.y * 128;
    const float* xb = xin ? (xin + (size_t)b * C * NPTS)
                          : (g_cat + (size_t)b * 512 * NPTS + (size_t)cin_off * NPTS);
    __shared__ __align__(16) float As[8][128];
    __shared__ __align__(16) float Bs[8][128];
    const int tid = threadIdx.x;
    const int tx = tid & 15, ty = tid >> 4;

    float acc[8][8];
    #pragma unroll
    for (int i = 0; i < 8; i++)
        #pragma unroll
        for (int j = 0; j < 8; j++) acc[i][j] = 0.f;

    const int NCH = (C + 7) / 8;
    for (int ch = 0; ch < NCH; ch++) {
        const int c0 = ch * 8;
        #pragma unroll
        for (int i = 0; i < 4; i++) {
            int idx = tid + i * 256;
            int r = idx >> 7, col = idx & 127;
            int c = c0 + r;
            As[r][col] = (c < C) ? xb[(size_t)c * NPTS + n0 + col] : 0.f;
            Bs[r][col] = (c < C) ? xb[(size_t)c * NPTS + m0 + col] : 0.f;
        }
        __syncthreads();
        #pragma unroll
        for (int r = 0; r < 8; r++) {
            float4 a0 = *(const float4*)&As[r][ty * 8];
            float4 a1 = *(const float4*)&As[r][ty * 8 + 4];
            float4 b0 = *(const float4*)&Bs[r][tx * 8];
            float4 b1 = *(const float4*)&Bs[r][tx * 8 + 4];
            float av[8] = {a0.x, a0.y, a0.z, a0.w, a1.x, a1.y, a1.z, a1.w};
            float bv[8] = {b0.x, b0.y, b0.z, b0.w, b1.x, b1.y, b1.z, b1.w};
            #pragma unroll
            for (int i = 0; i < 8; i++)
                #pragma unroll
                for (int j = 0; j < 8; j++)
                    acc[i][j] = fmaf(av[i], bv[j], acc[i][j]);
        }
        __syncthreads();
    }

    #pragma unroll
    for (int i = 0; i < 8; i++) {
        float* Gr = g_gram + ((size_t)b * NPTS + n0 + ty * 8 + i) * NPTS + m0 + tx * 8;
        *(float4*)Gr       = make_float4(acc[i][0], acc[i][1], acc[i][2], acc[i][3]);
        *(float4*)(Gr + 4) = make_float4(acc[i][4], acc[i][5], acc[i][6], acc[i][7]);
    }
}

__global__ void __launch_bounds__(256) topk_kernel() {
    const int tid = threadIdx.x;
    const int lane = tid & 31;
    const int gw = blockIdx.x * 8 + (tid >> 5);
    const int b = gw >> 10, n = gw & 1023;

    const float* Grow = g_gram + ((size_t)b * NPTS + n) * NPTS;
    const float* xxb = g_xx + b * NPTS;

    float d[32];
    #pragma unroll
    for (int j = 0; j < 32; j++) {
        int m = j * 32 + lane;
        d[j] = 2.f * Grow[m] - xxb[m];
    }

    int* myidx = g_idx + ((size_t)b * NPTS + n) * KNB;
    for (int k = 0; k < KNB; k++) {
        float bv = -INFINITY; int bj = 0;
        #pragma unroll
        for (int j = 0; j < 32; j++) {
            if (d[j] > bv) { bv = d[j]; bj = j; }
        }
        int bidx = bj * 32 + lane;
        #pragma unroll
        for (int off = 16; off > 0; off >>= 1) {
            float ov = __shfl_xor_sync(0xffffffffu, bv, off);
            int   oi = __shfl_xor_sync(0xffffffffu, bidx, off);
            if (ov > bv || (ov == bv && oi < bidx)) { bv = ov; bidx = oi; }
        }
        if (lane == (bidx & 31)) {
            int jj = bidx >> 5;
            #pragma unroll
            for (int j = 0; j < 32; j++)
                if (j == jj) d[j] = -INFINITY;
        }
        if (lane == 0) myidx[k] = bidx;
    }
}

// ================= MLP head =================
__global__ void mlp_bn_kernel(const float* __restrict__ w, const float* __restrict__ bnp,
                              const float* __restrict__ hin, float* __restrict__ hout,
                              int IN, int ON) {
    const int b = blockIdx.x, o = threadIdx.x;
    const float* hr = hin + (size_t)b * IN;
    const float* wr = w + (size_t)o * IN;
    float a0 = 0.f, a1 = 0.f, a2 = 0.f, a3 = 0.f;
    for (int c = 0; c < IN; c += 4) {
        a0 = fmaf(hr[c],     wr[c],     a0);
        a1 = fmaf(hr[c + 1], wr[c + 1], a1);
        a2 = fmaf(hr[c + 2], wr[c + 2], a2);
        a3 = fmaf(hr[c + 3], wr[c + 3], a3);
    }
    float acc = (a0 + a1) + (a2 + a3);
    float gg = bnp[o], bb = bnp[ON + o], mm = bnp[2 * ON + o], vv = bnp[3 * ON + o];
    float scale = gg / sqrtf(vv + CEPS);
    float y = (acc - mm) * scale + bb;
    hout[(size_t)b * ON + o] = (y > 0.f) ? y : CSLOPE * y;
}

__global__ void final_kernel(const float* __restrict__ w, const float* __restrict__ bias,
                             float* __restrict__ out) {
    const int b = blockIdx.x, o = threadIdx.x;
    const float* hr = g_h2 + b * 256;
    const float* wr = w + (size_t)o * 256;
    float a0 = 0.f, a1 = 0.f, a2 = 0.f, a3 = 0.f;
    for (int c = 0; c < 256; c += 4) {
        a0 = fmaf(hr[c],     wr[c],     a0);
        a1 = fmaf(hr[c + 1], wr[c + 1], a1);
        a2 = fmaf(hr[c + 2], wr[c + 2], a2);
        a3 = fmaf(hr[c + 3], wr[c + 3], a3);
    }
    out[b * 64 + o] = bias[o] + (a0 + a1) + (a2 + a3);
}

// ================= launch =================
extern "C" void kernel_launch(void* const* d_in, const int* in_sizes, int n_in,
                              void* d_out, int out_size) {
    const float* x    = (const float*)d_in[0];
    const float* w0   = (const float*)d_in[1];
    const float* w1   = (const float*)d_in[2];
    const float* w2   = (const float*)d_in[3];
    const float* w3   = (const float*)d_in[4];
    const float* bn0  = (const float*)d_in[5];
    const float* bn1  = (const float*)d_in[6];
    const float* bn2  = (const float*)d_in[7];
    const float* bn3  = (const float*)d_in[8];
    const float* we   = (const float*)d_in[9];
    const float* bne  = (const float*)d_in[10];
    const float* wf0  = (const float*)d_in[11];
    const float* bnf0 = (const float*)d_in[12];
    const float* wf1  = (const float*)d_in[13];
    const float* bnf1 = (const float*)d_in[14];
    const float* wfin = (const float*)d_in[15];
    const float* bfin = (const float*)d_in[16];

    float *h0, *h1, *h2, *Fp, *Yp, *Wtp, *catp, *gramp;
    cudaGetSymbolAddress((void**)&h0, g_h0);
    cudaGetSymbolAddress((void**)&h1, g_h1);
    cudaGetSymbolAddress((void**)&h2, g_h2);
    cudaGetSymbolAddress((void**)&Fp, g_F);
    cudaGetSymbolAddress((void**)&Yp, g_Y);
    cudaGetSymbolAddress((void**)&Wtp, g_Wt);
    cudaGetSymbolAddress((void**)&catp, g_cat);
    cudaGetSymbolAddress((void**)&gramp, g_gram);

    dim3 gxx(NPTS / 256, BATCH);
    dim3 ggr(8, 8, BATCH);
    dim3 gpn(NPTS, BATCH);
    dim3 tb(32, 8);

    // ---- block 1: x (C=3) -> x1 (64) at cat[0:64] ----
    xx_kernel<3><<<gxx, 256>>>(x, 0);
    gram_kernel<3><<<ggr, 256>>>(x, 0);
    topk_kernel<<<1024, 256>>>();
    transpose_kernel<<<dim3(32, 1, BATCH), tb>>>(x, 0, 3, 4);
    fbuild_kernel<<<gpn, 256>>>(3, 32, 4);
    wprep_kernel<<<(32 * 64 + 255) / 256, 256>>>(w0, 6, 32, 64);
    gemm_tf32<64><<<dim3(1, MTOT / 128, 1), 256>>>(Fp, Wtp, Yp, 32, 32, 64, 64, 0, 0, 0);
    cepi_kernel<<<gpn, 64>>>(bn0, 64, 0);

    // ---- block 2: x1 (C=64) -> x2 (64) at cat[64:128] ----
    xx_kernel<64><<<gxx, 256>>>(nullptr, 0);
    gram_kernel<64><<<ggr, 256>>>(nullptr, 0);
    topk_kernel<<<1024, 256>>>();
    transpose_kernel<<<dim3(32, 2, BATCH), tb>>>(nullptr, 0, 64, 64);
    fbuild_kernel<<<gpn, 256>>>(64, 128, 64);
    wprep_kernel<<<(128 * 64 + 255) / 256, 256>>>(w1, 128, 128, 64);
    gemm_tf32<64><<<dim3(1, MTOT / 128, 1), 256>>>(Fp, Wtp, Yp, 128, 128, 64, 64, 0, 0, 0);
    cepi_kernel<<<gpn, 64>>>(bn1, 64, 64);

    // ---- block 3: x2 (C=64) -> x3 (128) at cat[128:256] ----
    xx_kernel<64><<<gxx, 256>>>(nullptr, 64);
    gram_kernel<64><<<ggr, 256>>>(nullptr, 64);
    topk_kernel<<<1024, 256>>>();
    transpose_kernel<<<dim3(32, 2, BATCH), tb>>>(nullptr, 64, 64, 64);
    fbuild_kernel<<<gpn, 256>>>(64, 128, 64);
    wprep_kernel<<<(128 * 128 + 255) / 256, 256>>>(w2, 128, 128, 128);
    gemm_tf32<128><<<dim3(1, MTOT / 128, 1), 256>>>(Fp, Wtp, Yp, 128, 128, 128, 128, 0, 0, 0);
    cepi_kernel<<<gpn, 128>>>(bn2, 128, 128);

    // ---- block 4: x3 (C=128) -> x4 (256) at cat[256:512] ----
    xx_kernel<128><<<gxx, 256>>>(nullptr, 128);
    gram_kernel<128><<<ggr, 256>>>(nullptr, 128);
    topk_kernel<<<1024, 256>>>();
    transpose_kernel<<<dim3(32, 4, BATCH), tb>>>(nullptr, 128, 128, 128);
    fbuild_kernel<<<gpn, 256>>>(128, 256, 128);
    wprep_kernel<<<(256 * 256 + 255) / 256, 256>>>(w3, 256, 256, 256);
    gemm_tf32<128><<<dim3(2, MTOT / 128, 1), 256>>>(Fp, Wtp, Yp, 256, 256, 256, 256, 0, 0, 0);
    cepi_kernel<<<gpn, 256>>>(bn3, 256, 256);

    // ---- embedding: e[b][o][n] = we @ cat[b] into g_gram, then pool ----
    gemm_tf32<128><<<dim3(8, 8, BATCH), 256>>>(we, catp, gramp, 512, 512, NPTS, NPTS,
                                               0, (size_t)512 * NPTS, (size_t)NPTS * NPTS);
    epool_kernel<<<dim3(128, BATCH), 256>>>(bne);

    // ---- MLP head ----
    mlp_bn_kernel<<<BATCH, 512>>>(wf0, bnf0, h0, h1, 2048, 512);
    mlp_bn_kernel<<<BATCH, 256>>>(wf1, bnf1, h1, h2, 512, 256);
    final_kernel<<<BATCH, 64>>>(wfin, bfin, (float*)d_out);
}

// round 5
// speedup vs baseline: 6.5815x; 1.1652x over previous
#include <cuda_runtime.h>
#include <math.h>
#include <stdint.h>

#define NPTS 1024
#define KNB 20
#define BATCH 8
#define CEPS 1e-5f
#define CSLOPE 0.2f

// ---------------- scratch (no allocations allowed) ----------------
__device__ float g_cat[(size_t)BATCH * 512 * NPTS];   // x1(0:64) x2(64:128) x3(128:256) x4(256:512)
__device__ float g_gram[(size_t)BATCH * NPTS * NPTS]; // gram; later reused as edge activations e[b][o][n]
__device__ float g_xx[BATCH * NPTS];
__device__ int   g_idx[(size_t)BATCH * NPTS * KNB];
__device__ float g_xT[(size_t)BATCH * NPTS * 128];    // transposed features [b*NPTS+n][ldT]
__device__ float g_Z[(size_t)BATCH * NPTS * 512];     // Z = xT @ [W1t | Wdt]  (8192 x 2O)
__device__ float g_Wt[256 * 512];                     // packed [KP][2O]
__device__ float g_h0[BATCH * 2048];
__device__ float g_h1[BATCH * 512];
__device__ float g_h2[BATCH * 256];

// ================= tf32 MMA helpers =================
__device__ __forceinline__ uint32_t f2tf(float f) {
    uint32_t u; asm("cvt.rna.tf32.f32 %0, %1;" : "=r"(u) : "f"(f)); return u;
}
__device__ __forceinline__ void mma8(float* c, const uint32_t* a, const uint32_t* b) {
    asm volatile(
        "mma.sync.aligned.m16n8k8.row.col.f32.tf32.tf32.f32 "
        "{%0,%1,%2,%3}, {%4,%5,%6,%7}, {%8,%9}, {%0,%1,%2,%3};\n"
        : "+f"(c[0]), "+f"(c[1]), "+f"(c[2]), "+f"(c[3])
        : "r"(a[0]), "r"(a[1]), "r"(a[2]), "r"(a[3]), "r"(b[0]), "r"(b[1]));
}

// ================= 3xTF32 split-precision GEMM =================
// C[M][N] = A[M][K] (row-major) x B[K][N] (row-major), fp32-grade accuracy:
// A = Ah + Al, B = Bh + Bl;  C ~= AhBh + AlBh + AhBl.
// 128 x TN block tile, 8 warps (2x4), KC=16 k-chunk.
template<int TN>
__global__ void __launch_bounds__(256, 1) gemm_split(
    const float* __restrict__ A, const float* __restrict__ B, float* __restrict__ Cc,
    int K, int lda, int ldb, int ldc,
    size_t sAz, size_t sBz, size_t sCz)
{
    constexpr int KC = 16;
    constexpr int NT = TN / 32;             // n mma-tiles per warp
    constexpr int NB4 = (KC * TN) / 1024;   // B float4 loads per thread (TN=128->2, 64->1)

    const int z = blockIdx.z;
    const int m0 = blockIdx.y * 128, n0 = blockIdx.x * TN;
    const float* Ab = A + z * sAz + (size_t)m0 * lda;
    const float* Bb = B + z * sBz + n0;
    float* Cb = Cc + z * sCz;

    __shared__ uint32_t Ash[128][KC + 4], Asl[128][KC + 4];
    __shared__ uint32_t Bsh[KC][TN + 8],  Bsl[KC][TN + 8];

    const int tid = threadIdx.x, lane = tid & 31, wrp = tid >> 5;
    const int wm = wrp >> 2, wn = wrp & 3;
    const int qr = lane >> 2, qc = lane & 3;

    float acc[4][NT][4];
    #pragma unroll
    for (int i = 0; i < 4; i++)
        #pragma unroll
        for (int j = 0; j < NT; j++)
            #pragma unroll
            for (int q = 0; q < 4; q++) acc[i][j][q] = 0.f;

    int ar[2], ac[2];
    #pragma unroll
    for (int i = 0; i < 2; i++) { int idx = tid + i * 256; ar[i] = idx >> 2; ac[i] = (idx & 3) * 4; }
    int br[NB4], bc[NB4];
    #pragma unroll
    for (int i = 0; i < NB4; i++) { int idx = tid + i * 256; br[i] = idx / (TN / 4); bc[i] = (idx % (TN / 4)) * 4; }

    float4 ra[2], rb[NB4];
    #pragma unroll
    for (int i = 0; i < 2; i++) ra[i] = *(const float4*)(Ab + (size_t)ar[i] * lda + ac[i]);
    #pragma unroll
    for (int i = 0; i < NB4; i++) rb[i] = *(const float4*)(Bb + (size_t)br[i] * ldb + bc[i]);

    const int KT = K / KC;
    for (int kt = 0; kt < KT; kt++) {
        #pragma unroll
        for (int i = 0; i < 2; i++) {
            float v[4] = {ra[i].x, ra[i].y, ra[i].z, ra[i].w};
            #pragma unroll
            for (int q = 0; q < 4; q++) {
                uint32_t h = f2tf(v[q]);
                Ash[ar[i]][ac[i] + q] = h;
                Asl[ar[i]][ac[i] + q] = f2tf(v[q] - __uint_as_float(h));
            }
        }
        #pragma unroll
        for (int i = 0; i < NB4; i++) {
            float v[4] = {rb[i].x, rb[i].y, rb[i].z, rb[i].w};
            #pragma unroll
            for (int q = 0; q < 4; q++) {
                uint32_t h = f2tf(v[q]);
                Bsh[br[i]][bc[i] + q] = h;
                Bsl[br[i]][bc[i] + q] = f2tf(v[q] - __uint_as_float(h));
            }
        }
        __syncthreads();
        if (kt + 1 < KT) {
            const float* An = Ab + (kt + 1) * KC;
            const float* Bn = Bb + (size_t)(kt + 1) * KC * ldb;
            #pragma unroll
            for (int i = 0; i < 2; i++) ra[i] = *(const float4*)(An + (size_t)ar[i] * lda + ac[i]);
            #pragma unroll
            for (int i = 0; i < NB4; i++) rb[i] = *(const float4*)(Bn + (size_t)br[i] * ldb + bc[i]);
        }
        #pragma unroll
        for (int kk = 0; kk < 2; kk++) {
            uint32_t afh[4][4], afl[4][4];
            #pragma unroll
            for (int mt = 0; mt < 4; mt++) {
                int r = wm * 64 + mt * 16 + qr, c = kk * 8 + qc;
                afh[mt][0] = Ash[r][c];     afh[mt][1] = Ash[r + 8][c];
                afh[mt][2] = Ash[r][c + 4]; afh[mt][3] = Ash[r + 8][c + 4];
                afl[mt][0] = Asl[r][c];     afl[mt][1] = Asl[r + 8][c];
                afl[mt][2] = Asl[r][c + 4]; afl[mt][3] = Asl[r + 8][c + 4];
            }
            uint32_t bfh[NT][2], bfl[NT][2];
            #pragma unroll
            for (int nt = 0; nt < NT; nt++) {
                int cc = wn * (TN / 4) + nt * 8 + qr, rr = kk * 8 + qc;
                bfh[nt][0] = Bsh[rr][cc]; bfh[nt][1] = Bsh[rr + 4][cc];
                bfl[nt][0] = Bsl[rr][cc]; bfl[nt][1] = Bsl[rr + 4][cc];
            }
            #pragma unroll
            for (int mt = 0; mt < 4; mt++)
                #pragma unroll
                for (int nt = 0; nt < NT; nt++) {
                    mma8(acc[mt][nt], afh[mt], bfh[nt]);
                    mma8(acc[mt][nt], afl[mt], bfh[nt]);
                    mma8(acc[mt][nt], afh[mt], bfl[nt]);
                }
        }
        __syncthreads();
    }

    #pragma unroll
    for (int mt = 0; mt < 4; mt++) {
        #pragma unroll
        for (int nt = 0; nt < NT; nt++) {
            int r = m0 + wm * 64 + mt * 16 + qr;
            int cc = n0 + wn * (TN / 4) + nt * 8 + 2 * qc;
            *(float2*)(Cb + (size_t)r * ldc + cc)       = make_float2(acc[mt][nt][0], acc[mt][nt][1]);
            *(float2*)(Cb + (size_t)(r + 8) * ldc + cc) = make_float2(acc[mt][nt][2], acc[mt][nt][3]);
        }
    }
}

// ================= support kernels =================

// transpose xb[c][n] -> g_xT[b*NPTS+n][ldT], zero-padding cols C..ldT
__global__ void transpose_kernel(const float* __restrict__ xin, int cin_off, int C, int ldT) {
    const int b = blockIdx.z;
    const float* xb = xin ? (xin + (size_t)b * C * NPTS)
                          : (g_cat + (size_t)b * 512 * NPTS + (size_t)cin_off * NPTS);
    __shared__ float t[32][33];
    const int n0 = blockIdx.x * 32, c0 = blockIdx.y * 32;
    const int tx = threadIdx.x, ty = threadIdx.y;
    #pragma unroll
    for (int i = 0; i < 32; i += 8) {
        int c = c0 + ty + i;
        t[ty + i][tx] = (c < C) ? xb[(size_t)c * NPTS + n0 + tx] : 0.f;
    }
    __syncthreads();
    #pragma unroll
    for (int i = 0; i < 32; i += 8) {
        int n = n0 + ty + i, c = c0 + tx;
        if (c < ldT) g_xT[((size_t)b * NPTS + n) * ldT + c] = t[tx][ty + i];
    }
}

// pack [KP][2O]: cols [0,O) = w[o][kp] (W1), cols [O,2O) = w[o][C+kp]-w[o][kp]
__global__ void wprep2_kernel(const float* __restrict__ w, int C, int KP, int O) {
    int i = blockIdx.x * 256 + threadIdx.x;
    int N2 = 2 * O;
    if (i >= KP * N2) return;
    int kp = i / N2, j = i - kp * N2;
    float v;
    if (j < O) v = (kp < C) ? w[(size_t)j * 2 * C + kp] : 0.f;
    else { int o = j - O; v = (kp < C) ? (w[(size_t)o * 2 * C + C + kp] - w[(size_t)o * 2 * C + kp]) : 0.f; }
    g_Wt[i] = v;
}

// conv epilogue from Z: max_k Z1[jid_k][o] + Z2[n][o], then BN (gamma>0) + lrelu
__global__ void cepi_kernel(const float* __restrict__ bnp, int O, int cout_off) {
    const int b = blockIdx.y, n = blockIdx.x, o = threadIdx.x;
    __shared__ int jid[KNB];
    if (o < KNB) jid[o] = g_idx[((size_t)b * NPTS + n) * KNB + o];
    __syncthreads();
    const int ld = 2 * O;
    const size_t rowbase = (size_t)b * NPTS;
    float mx = -INFINITY;
    #pragma unroll 4
    for (int k = 0; k < KNB; k++)
        mx = fmaxf(mx, g_Z[(rowbase + jid[k]) * ld + o]);
    mx += g_Z[(rowbase + n) * ld + O + o];
    float gg = bnp[o], bb = bnp[O + o], mm = bnp[2 * O + o], vv = bnp[3 * O + o];
    float scale = gg / sqrtf(vv + CEPS);
    float y = (mx - mm) * scale + bb;
    y = (y > 0.f) ? y : CSLOPE * y;
    g_cat[(size_t)b * 512 * NPTS + (size_t)(cout_off + o) * NPTS + n] = y;
}

// edge pool: e[b][o][n] raw in g_gram -> BN + lrelu -> max & mean over n
__global__ void epool_kernel(const float* __restrict__ bne) {
    const int b = blockIdx.y;
    const int w = threadIdx.x >> 5, lane = threadIdx.x & 31;
    const int o = blockIdx.x * 8 + w;
    const float* er = g_gram + ((size_t)b * 1024 + o) * NPTS;
    float gg = bne[o], bb = bne[1024 + o], mm = bne[2048 + o], vv = bne[3072 + o];
    float scale = gg / sqrtf(vv + CEPS);
    float mx = -INFINITY, sm = 0.f;
    for (int i = lane; i < NPTS; i += 32) {
        float y = (er[i] - mm) * scale + bb;
        y = (y > 0.f) ? y : CSLOPE * y;
        mx = fmaxf(mx, y);
        sm += y;
    }
    #pragma unroll
    for (int off = 16; off > 0; off >>= 1) {
        mx = fmaxf(mx, __shfl_xor_sync(0xffffffffu, mx, off));
        sm += __shfl_xor_sync(0xffffffffu, sm, off);
    }
    if (lane == 0) {
        g_h0[b * 2048 + o] = mx;
        g_h0[b * 2048 + 1024 + o] = sm * (1.0f / 1024.0f);
    }
}

// ================= kNN support =================
template<int C>
__global__ void xx_kernel(const float* __restrict__ xin, int cin_off) {
    const int b = blockIdx.y;
    const int m = blockIdx.x * 256 + threadIdx.x;
    const float* xb = xin ? (xin + (size_t)b * C * NPTS)
                          : (g_cat + (size_t)b * 512 * NPTS + (size_t)cin_off * NPTS);
    float s = 0.f;
    #pragma unroll 8
    for (int c = 0; c < C; c++) {
        float v = xb[(size_t)c * NPTS + m];
        s = fmaf(v, v, s);
    }
    g_xx[b * NPTS + m] = s;
}

// exact scalar gram for C=3 only (avoids K-padding OOB on the real input)
template<int C>
__global__ void __launch_bounds__(256) gram_kernel(const float* __restrict__ xin, int cin_off) {
    const int b = blockIdx.z;
    const int m0 = blockIdx.x * 128, n0 = blockIdx.y * 128;
    const float* xb = xin ? (xin + (size_t)b * C * NPTS)
                          : (g_cat + (size_t)b * 512 * NPTS + (size_t)cin_off * NPTS);
    __shared__ __align__(16) float As[8][128];
    __shared__ __align__(16) float Bs[8][128];
    const int tid = threadIdx.x;
    const int tx = tid & 15, ty = tid >> 4;

    float acc[8][8];
    #pragma unroll
    for (int i = 0; i < 8; i++)
        #pragma unroll
        for (int j = 0; j < 8; j++) acc[i][j] = 0.f;

    const int NCH = (C + 7) / 8;
    for (int ch = 0; ch < NCH; ch++) {
        const int c0 = ch * 8;
        #pragma unroll
        for (int i = 0; i < 4; i++) {
            int idx = tid + i * 256;
            int r = idx >> 7, col = idx & 127;
            int c = c0 + r;
            As[r][col] = (c < C) ? xb[(size_t)c * NPTS + n0 + col] : 0.f;
            Bs[r][col] = (c < C) ? xb[(size_t)c * NPTS + m0 + col] : 0.f;
        }
        __syncthreads();
        #pragma unroll
        for (int r = 0; r < 8; r++) {
            float4 a0 = *(const float4*)&As[r][ty * 8];
            float4 a1 = *(const float4*)&As[r][ty * 8 + 4];
            float4 b0 = *(const float4*)&Bs[r][tx * 8];
            float4 b1 = *(const float4*)&Bs[r][tx * 8 + 4];
            float av[8] = {a0.x, a0.y, a0.z, a0.w, a1.x, a1.y, a1.z, a1.w};
            float bv[8] = {b0.x, b0.y, b0.z, b0.w, b1.x, b1.y, b1.z, b1.w};
            #pragma unroll
            for (int i = 0; i < 8; i++)
                #pragma unroll
                for (int j = 0; j < 8; j++)
                    acc[i][j] = fmaf(av[i], bv[j], acc[i][j]);
        }
        __syncthreads();
    }

    #pragma unroll
    for (int i = 0; i < 8; i++) {
        float* Gr = g_gram + ((size_t)b * NPTS + n0 + ty * 8 + i) * NPTS + m0 + tx * 8;
        *(float4*)Gr       = make_float4(acc[i][0], acc[i][1], acc[i][2], acc[i][3]);
        *(float4*)(Gr + 4) = make_float4(acc[i][4], acc[i][5], acc[i][6], acc[i][7]);
    }
}

__global__ void __launch_bounds__(256) topk_kernel() {
    const int tid = threadIdx.x;
    const int lane = tid & 31;
    const int gw = blockIdx.x * 8 + (tid >> 5);
    const int b = gw >> 10, n = gw & 1023;

    const float* Grow = g_gram + ((size_t)b * NPTS + n) * NPTS;
    const float* xxb = g_xx + b * NPTS;

    float d[32];
    #pragma unroll
    for (int j = 0; j < 32; j++) {
        int m = j * 32 + lane;
        d[j] = 2.f * Grow[m] - xxb[m];
    }

    int* myidx = g_idx + ((size_t)b * NPTS + n) * KNB;
    for (int k = 0; k < KNB; k++) {
        float bv = -INFINITY; int bj = 0;
        #pragma unroll
        for (int j = 0; j < 32; j++) {
            if (d[j] > bv) { bv = d[j]; bj = j; }
        }
        int bidx = bj * 32 + lane;
        #pragma unroll
        for (int off = 16; off > 0; off >>= 1) {
            float ov = __shfl_xor_sync(0xffffffffu, bv, off);
            int   oi = __shfl_xor_sync(0xffffffffu, bidx, off);
            if (ov > bv || (ov == bv && oi < bidx)) { bv = ov; bidx = oi; }
        }
        if (lane == (bidx & 31)) {
            int jj = bidx >> 5;
            #pragma unroll
            for (int j = 0; j < 32; j++)
                if (j == jj) d[j] = -INFINITY;
        }
        if (lane == 0) myidx[k] = bidx;
    }
}

// ================= MLP head =================
__global__ void mlp_bn_kernel(const float* __restrict__ w, const float* __restrict__ bnp,
                              const float* __restrict__ hin, float* __restrict__ hout,
                              int IN, int ON) {
    const int b = blockIdx.x, o = threadIdx.x;
    const float* hr = hin + (size_t)b * IN;
    const float* wr = w + (size_t)o * IN;
    float a0 = 0.f, a1 = 0.f, a2 = 0.f, a3 = 0.f;
    for (int c = 0; c < IN; c += 4) {
        a0 = fmaf(hr[c],     wr[c],     a0);
        a1 = fmaf(hr[c + 1], wr[c + 1], a1);
        a2 = fmaf(hr[c + 2], wr[c + 2], a2);
        a3 = fmaf(hr[c + 3], wr[c + 3], a3);
    }
    float acc = (a0 + a1) + (a2 + a3);
    float gg = bnp[o], bb = bnp[ON + o], mm = bnp[2 * ON + o], vv = bnp[3 * ON + o];
    float scale = gg / sqrtf(vv + CEPS);
    float y = (acc - mm) * scale + bb;
    hout[(size_t)b * ON + o] = (y > 0.f) ? y : CSLOPE * y;
}

__global__ void final_kernel(const float* __restrict__ w, const float* __restrict__ bias,
                             float* __restrict__ out) {
    const int b = blockIdx.x, o = threadIdx.x;
    const float* hr = g_h2 + b * 256;
    const float* wr = w + (size_t)o * 256;
    float a0 = 0.f, a1 = 0.f, a2 = 0.f, a3 = 0.f;
    for (int c = 0; c < 256; c += 4) {
        a0 = fmaf(hr[c],     wr[c],     a0);
        a1 = fmaf(hr[c + 1], wr[c + 1], a1);
        a2 = fmaf(hr[c + 2], wr[c + 2], a2);
        a3 = fmaf(hr[c + 3], wr[c + 3], a3);
    }
    out[b * 64 + o] = bias[o] + (a0 + a1) + (a2 + a3);
}

// ================= launch =================
extern "C" void kernel_launch(void* const* d_in, const int* in_sizes, int n_in,
                              void* d_out, int out_size) {
    const float* x    = (const float*)d_in[0];
    const float* w0   = (const float*)d_in[1];
    const float* w1   = (const float*)d_in[2];
    const float* w2   = (const float*)d_in[3];
    const float* w3   = (const float*)d_in[4];
    const float* bn0  = (const float*)d_in[5];
    const float* bn1  = (const float*)d_in[6];
    const float* bn2  = (const float*)d_in[7];
    const float* bn3  = (const float*)d_in[8];
    const float* we   = (const float*)d_in[9];
    const float* bne  = (const float*)d_in[10];
    const float* wf0  = (const float*)d_in[11];
    const float* bnf0 = (const float*)d_in[12];
    const float* wf1  = (const float*)d_in[13];
    const float* bnf1 = (const float*)d_in[14];
    const float* wfin = (const float*)d_in[15];
    const float* bfin = (const float*)d_in[16];

    float *h0, *h1, *h2, *Zp, *Wtp, *catp, *gramp, *xTp;
    cudaGetSymbolAddress((void**)&h0, g_h0);
    cudaGetSymbolAddress((void**)&h1, g_h1);
    cudaGetSymbolAddress((void**)&h2, g_h2);
    cudaGetSymbolAddress((void**)&Zp, g_Z);
    cudaGetSymbolAddress((void**)&Wtp, g_Wt);
    cudaGetSymbolAddress((void**)&catp, g_cat);
    cudaGetSymbolAddress((void**)&gramp, g_gram);
    cudaGetSymbolAddress((void**)&xTp, g_xT);

    dim3 gxx(NPTS / 256, BATCH);
    dim3 gpn(NPTS, BATCH);
    dim3 tb(32, 8);
    const size_t sA = (size_t)NPTS;            // per-batch xT row stride factor (x ldT applied below)
    const size_t sB = (size_t)512 * NPTS;
    const size_t sC = (size_t)NPTS * NPTS;

    // ---- block 1: x (C=3, pad 32) -> x1 (64) at cat[0:64] ----
    transpose_kernel<<<dim3(32, 1, BATCH), tb>>>(x, 0, 3, 32);
    xx_kernel<3><<<gxx, 256>>>(x, 0);
    gram_kernel<3><<<dim3(8, 8, BATCH), 256>>>(x, 0);
    topk_kernel<<<1024, 256>>>();
    wprep2_kernel<<<(32 * 128 + 255) / 256, 256>>>(w0, 3, 32, 64);
    gemm_split<64><<<dim3(2, 64, 1), 256>>>(xTp, Wtp, Zp, 32, 32, 128, 128, 0, 0, 0);
    cepi_kernel<<<gpn, 64>>>(bn0, 64, 0);

    // ---- block 2: x1 (C=64) -> x2 (64) at cat[64:128] ----
    transpose_kernel<<<dim3(32, 2, BATCH), tb>>>(nullptr, 0, 64, 64);
    xx_kernel<64><<<gxx, 256>>>(nullptr, 0);
    gemm_split<128><<<dim3(8, 8, BATCH), 256>>>(xTp, catp, gramp, 64, 64, NPTS, NPTS,
                                                sA * 64, sB, sC);
    topk_kernel<<<1024, 256>>>();
    wprep2_kernel<<<(64 * 128 + 255) / 256, 256>>>(w1, 64, 64, 64);
    gemm_split<64><<<dim3(2, 64, 1), 256>>>(xTp, Wtp, Zp, 64, 64, 128, 128, 0, 0, 0);
    cepi_kernel<<<gpn, 64>>>(bn1, 64, 64);

    // ---- block 3: x2 (C=64) -> x3 (128) at cat[128:256] ----
    transpose_kernel<<<dim3(32, 2, BATCH), tb>>>(nullptr, 64, 64, 64);
    xx_kernel<64><<<gxx, 256>>>(nullptr, 64);
    gemm_split<128><<<dim3(8, 8, BATCH), 256>>>(xTp, catp + (size_t)64 * NPTS, gramp, 64, 64, NPTS, NPTS,
                                                sA * 64, sB, sC);
    topk_kernel<<<1024, 256>>>();
    wprep2_kernel<<<(64 * 256 + 255) / 256, 256>>>(w2, 64, 64, 128);
    gemm_split<128><<<dim3(2, 64, 1), 256>>>(xTp, Wtp, Zp, 64, 64, 256, 256, 0, 0, 0);
    cepi_kernel<<<gpn, 128>>>(bn2, 128, 128);

    // ---- block 4: x3 (C=128) -> x4 (256) at cat[256:512] ----
    transpose_kernel<<<dim3(32, 4, BATCH), tb>>>(nullptr, 128, 128, 128);
    xx_kernel<128><<<gxx, 256>>>(nullptr, 128);
    gemm_split<128><<<dim3(8, 8, BATCH), 256>>>(xTp, catp + (size_t)128 * NPTS, gramp, 128, 128, NPTS, NPTS,
                                                sA * 128, sB, sC);
    topk_kernel<<<1024, 256>>>();
    wprep2_kernel<<<(128 * 512 + 255) / 256, 256>>>(w3, 128, 128, 256);
    gemm_split<128><<<dim3(4, 64, 1), 256>>>(xTp, Wtp, Zp, 128, 128, 512, 512, 0, 0, 0);
    cepi_kernel<<<gpn, 256>>>(bn3, 256, 256);

    // ---- embedding: e[b][o][n] = we @ cat[b] into g_gram, then pool ----
    gemm_split<128><<<dim3(8, 8, BATCH), 256>>>(we, catp, gramp, 512, 512, NPTS, NPTS,
                                                0, sB, sC);
    epool_kernel<<<dim3(128, BATCH), 256>>>(bne);

    // ---- MLP head ----
    mlp_bn_kernel<<<BATCH, 512>>>(wf0, bnf0, h0, h1, 2048, 512);
    mlp_bn_kernel<<<BATCH, 256>>>(wf1, bnf1, h1, h2, 512, 256);
    final_kernel<<<BATCH, 64>>>(wfin, bfin, (float*)d_out);
}